// round 4
// baseline (speedup 1.0000x reference)
#include <cuda_runtime.h>
#include <cstdint>

// 3-layer GRU (gate order r,z,n), B=128, T=512, H=512, fp32.
// Persistent wavefront: tick k -> layer l computes t = k - l; double-buffered
// h state (parity k&1), one grid barrier per tick.
// Warp = one hidden unit; weights register-resident as packed f32x2 pairs.
// Compute core uses Blackwell fma.rn.f32x2 (2 MACs/instr), 4-value reduction
// (r,z pre-added), 2-batch interleaved butterfly.

#define Bv 128
#define Tv 512
#define Hv 512
#define NWARP 12
#define NCTA 128
#define NTHR (NWARP * 32)
#define NTICK (Tv + 2)
#define CHUNK 8
#define NCHUNK (Bv / CHUNK)
#define SLOT_FLOATS (CHUNK * Hv)
#define SMEM_BYTES (2 * 3 * SLOT_FLOATS * 4)

typedef unsigned long long ull;

__device__ float g_h[3][2][Bv * Hv];
__device__ unsigned g_count = 0;
__device__ unsigned g_phase = 0;

__device__ __forceinline__ void gsync(unsigned target) {
    __syncthreads();
    if (threadIdx.x == 0) {
        __threadfence();
        unsigned a = atomicAdd(&g_count, 1u);
        if (a == NCTA - 1) {
            g_count = 0u;
            __threadfence();
            atomicAdd(&g_phase, 1u);
        } else {
            while (*((volatile unsigned*)&g_phase) < target) __nanosleep(32);
        }
    }
    __syncthreads();
}

__device__ __forceinline__ void cp16(uint32_t s, const float* g) {
    asm volatile("cp.async.cg.shared.global [%0], [%1], 16;" :: "r"(s), "l"(g));
}

#define FMA2(acc, a, b) \
    asm("fma.rn.f32x2 %0, %1, %2, %3;" : "=l"(acc) : "l"(a), "l"(b), "l"(acc))

__device__ __forceinline__ float unpack_sum(ull v) {
    unsigned lo, hi;
    asm("mov.b64 {%0, %1}, %2;" : "=r"(lo), "=r"(hi) : "l"(v));
    return __uint_as_float(lo) + __uint_as_float(hi);
}

__device__ __forceinline__ float sigf(float x) {
    return 1.f / (1.f + __expf(-x));
}
__device__ __forceinline__ float tanh_fast(float x) {
    x = fminf(fmaxf(x, -15.f), 15.f);
    float t = __expf(2.f * x);
    return (t - 1.f) / (t + 1.f);
}

__global__ void __launch_bounds__(NTHR, 1) gru_wavefront(
    const float* __restrict__ x,
    const float* __restrict__ Wih0, const float* __restrict__ Whh0,
    const float* __restrict__ bih0, const float* __restrict__ bhh0,
    const float* __restrict__ Wih1, const float* __restrict__ Whh1,
    const float* __restrict__ bih1, const float* __restrict__ bhh1,
    const float* __restrict__ Wih2, const float* __restrict__ Whh2,
    const float* __restrict__ bih2, const float* __restrict__ bhh2,
    float* __restrict__ y)
{
    extern __shared__ float sbuf[];   // [2 parity][3 slots][CHUNK*512]
    const int tid  = threadIdx.x;
    const int w    = tid >> 5;
    const int lane = tid & 31;
    const int unit = blockIdx.x * NWARP + w;   // 0..1535
    const int layer = unit >> 9;
    const int j     = unit & 511;

    const int lo = (blockIdx.x * NWARP) >> 9;
    const int hi = (blockIdx.x * NWARP + NWARP - 1) >> 9;
    const int inSlot = (layer == lo) ? 0 : 1;
    const int hSlot  = (layer == lo) ? 1 : 2;

    const float* Wih = (layer == 0) ? Wih0 : (layer == 1) ? Wih1 : Wih2;
    const float* Whh = (layer == 0) ? Whh0 : (layer == 1) ? Whh1 : Whh2;
    const float* bihp = (layer == 0) ? bih0 : (layer == 1) ? bih1 : bih2;
    const float* bhhp = (layer == 0) ? bhh0 : (layer == 1) ? bhh1 : bhh2;

    // Register-resident weights as packed f32x2 pairs.
    // Lane owns K in [lane*16, lane*16+16): per gate row 8 ull (=16 floats),
    // 3 ih rows + 3 hh rows -> 48 ull = 96 regs.
    ull wiu[3][8], whu[3][8];
    float brz0, brz1, bn_i, bn_h;
#pragma unroll
    for (int g = 0; g < 3; ++g) {
        const ulonglong2* pi = (const ulonglong2*)(Wih + ((size_t)(g * Hv + j)) * Hv + lane * 16);
        const ulonglong2* ph = (const ulonglong2*)(Whh + ((size_t)(g * Hv + j)) * Hv + lane * 16);
#pragma unroll
        for (int q = 0; q < 4; ++q) {
            ulonglong2 a = pi[q]; wiu[g][2 * q] = a.x; wiu[g][2 * q + 1] = a.y;
            ulonglong2 b = ph[q]; whu[g][2 * q] = b.x; whu[g][2 * q + 1] = b.y;
        }
    }
    brz0 = __ldg(bihp + 0 * Hv + j) + __ldg(bhhp + 0 * Hv + j);
    brz1 = __ldg(bihp + 1 * Hv + j) + __ldg(bhhp + 1 * Hv + j);
    bn_i = __ldg(bihp + 2 * Hv + j);
    bn_h = __ldg(bhhp + 2 * Hv + j);

    unsigned base = *((volatile unsigned*)&g_phase);

    {
        float* p = (float*)g_h;
        const int total = 3 * 2 * Bv * Hv;
        for (int i = blockIdx.x * NTHR + tid; i < total; i += NCTA * NTHR) p[i] = 0.f;
    }
    gsync(base + 1);

    for (int k = 0; k < NTICK; ++k) {
        const int t  = k - layer;
        const bool act = (t >= 0) && (t < Tv);
        const int rp = (k + 1) & 1;
        const int wp = k & 1;

        const int t_lo = k - lo;
        const bool act_lo = (t_lo >= 0) && (t_lo < Tv);
        const int t_hi = k - hi;
        const bool act_hi = (hi > lo) && (t_hi >= 0) && (t_hi < Tv);

        if (act_lo || act_hi) {
            const float* s0base; size_t s0str;
            if (lo == 0) { s0base = x + (size_t)t_lo * Hv; s0str = (size_t)Tv * Hv; }
            else         { s0base = g_h[lo - 1][rp];       s0str = (size_t)Hv;      }
            const float* s1base = g_h[lo][rp];
            const float* s2base = g_h[hi][rp];

            auto stage = [&](int c) {
                const int pb = (c & 1) * 3;
                const int b0 = c * CHUNK;
                if (act_lo) {
                    uint32_t d = (uint32_t)__cvta_generic_to_shared(sbuf + (size_t)(pb + 0) * SLOT_FLOATS);
                    for (int i = tid; i < CHUNK * 128; i += NTHR) {
                        int bl = i >> 7, off = (i & 127) << 2;
                        cp16(d + (((bl << 9) + off) << 2), s0base + (size_t)(b0 + bl) * s0str + off);
                    }
                }
                {
                    uint32_t d = (uint32_t)__cvta_generic_to_shared(sbuf + (size_t)(pb + 1) * SLOT_FLOATS);
                    for (int i = tid; i < CHUNK * 128; i += NTHR) {
                        int bl = i >> 7, off = (i & 127) << 2;
                        cp16(d + (((bl << 9) + off) << 2), s1base + (size_t)((b0 + bl) * Hv) + off);
                    }
                }
                if (act_hi) {
                    uint32_t d = (uint32_t)__cvta_generic_to_shared(sbuf + (size_t)(pb + 2) * SLOT_FLOATS);
                    for (int i = tid; i < CHUNK * 128; i += NTHR) {
                        int bl = i >> 7, off = (i & 127) << 2;
                        cp16(d + (((bl << 9) + off) << 2), s2base + (size_t)((b0 + bl) * Hv) + off);
                    }
                }
                asm volatile("cp.async.commit_group;");
            };

            stage(0);
            for (int c = 0; c < NCHUNK; ++c) {
                if (c + 1 < NCHUNK) {
                    stage(c + 1);
                    asm volatile("cp.async.wait_group 1;");
                } else {
                    asm volatile("cp.async.wait_group 0;");
                }
                __syncthreads();

                if (act) {
                    const float* inb = sbuf + (size_t)((c & 1) * 3 + inSlot) * SLOT_FLOATS;
                    const float* hb  = sbuf + (size_t)((c & 1) * 3 + hSlot ) * SLOT_FLOATS;
#pragma unroll 1
                    for (int bp = 0; bp < CHUNK; bp += 2) {
                        float v[8];   // (r, z, i_n, h_n) for bl=bp, bp+1
#pragma unroll
                        for (int half = 0; half < 2; ++half) {
                            const int bl = bp + half;
                            const ulonglong2* ain = (const ulonglong2*)(inb + bl * Hv + lane * 16);
                            const ulonglong2* ahh = (const ulonglong2*)(hb  + bl * Hv + lane * 16);
                            ull acc[6] = {0ull, 0ull, 0ull, 0ull, 0ull, 0ull};
#pragma unroll
                            for (int q = 0; q < 4; ++q) {
                                ulonglong2 a = ain[q];
#pragma unroll
                                for (int g = 0; g < 3; ++g) {
                                    FMA2(acc[g], wiu[g][2 * q],     a.x);
                                    FMA2(acc[g], wiu[g][2 * q + 1], a.y);
                                }
                            }
#pragma unroll
                            for (int q = 0; q < 4; ++q) {
                                ulonglong2 a = ahh[q];
#pragma unroll
                                for (int g = 0; g < 3; ++g) {
                                    FMA2(acc[3 + g], whu[g][2 * q],     a.x);
                                    FMA2(acc[3 + g], whu[g][2 * q + 1], a.y);
                                }
                            }
                            // 4-value pre-added reduction set:
                            v[half * 4 + 0] = unpack_sum(acc[0]) + unpack_sum(acc[3]); // i_r + h_r
                            v[half * 4 + 1] = unpack_sum(acc[1]) + unpack_sum(acc[4]); // i_z + h_z
                            v[half * 4 + 2] = unpack_sum(acc[2]);                      // i_n
                            v[half * 4 + 3] = unpack_sum(acc[5]);                      // h_n
                        }
                        // 8 independent butterfly reductions (2 batches x 4 vals)
#pragma unroll
                        for (int off = 16; off; off >>= 1) {
#pragma unroll
                            for (int i = 0; i < 8; ++i)
                                v[i] += __shfl_xor_sync(0xffffffffu, v[i], off);
                        }
#pragma unroll
                        for (int half = 0; half < 2; ++half) {
                            const int bl = bp + half;
                            const int b = c * CHUNK + bl;
                            if (lane == (b & 31)) {
                                float r = sigf(v[half * 4 + 0] + brz0);
                                float z = sigf(v[half * 4 + 1] + brz1);
                                float n = tanh_fast(v[half * 4 + 2] + bn_i +
                                                    r * (v[half * 4 + 3] + bn_h));
                                float hp = hb[bl * Hv + j];
                                float hv = (1.f - z) * n + z * hp;
                                if (layer == 2) {
                                    float xv = __ldg(x + ((size_t)b * Tv + t) * Hv + j);
                                    hv = (xv != 0.f) ? hv : 0.f;
                                    y[((size_t)b * Tv + t) * Hv + j] = hv;
                                }
                                g_h[layer][wp][(size_t)b * Hv + j] = hv;
                            }
                        }
                    }
                }
                __syncthreads();
            }
        }
        gsync(base + 2 + k);
    }
}

extern "C" void kernel_launch(void* const* d_in, const int* in_sizes, int n_in,
                              void* d_out, int out_size) {
    (void)in_sizes; (void)n_in; (void)out_size;
    cudaFuncSetAttribute(gru_wavefront,
                         cudaFuncAttributeMaxDynamicSharedMemorySize, SMEM_BYTES);
    gru_wavefront<<<NCTA, NTHR, SMEM_BYTES>>>(
        (const float*)d_in[0],
        (const float*)d_in[1],  (const float*)d_in[2],
        (const float*)d_in[3],  (const float*)d_in[4],
        (const float*)d_in[5],  (const float*)d_in[6],
        (const float*)d_in[7],  (const float*)d_in[8],
        (const float*)d_in[9],  (const float*)d_in[10],
        (const float*)d_in[11], (const float*)d_in[12],
        (float*)d_out);
}

// round 7
// speedup vs baseline: 4.7216x; 4.7216x over previous
#include <cuda_runtime.h>
#include <cuda_bf16.h>
#include <cstdint>

// 3-layer GRU (r,z,n), B=128, T=512, H=512, fp32 — mma.sync bf16 3-term hi/lo.
// Wavefront: tick k -> layer l computes t = k - l; one grid barrier per tick.
// 96 CTAs = 3 layers x 16 col-tiles (32 units) x 2 batch halves.
// Per tick each CTA: D[64,128] = A[64,3072] x B[128,3072]^T via m16n8k16 bf16
// mma.sync, K streamed in 128-chunks through a 3-stage cp.async smem ring.
// K regions (1024 each = [x 512 | h 512]):
//   r0: a_hi * w_hi     r1: a_lo * w_hi     r2: a_hi * w_lo
// so a*w is computed to ~2^-16 relative (only a_lo*w_lo dropped).
// Columns: [r(32), z(32), i_n(32), h_n(32)] (prep-permuted weights; i_n zero in
// h-half, h_n zero in x-half).

#define Bv 128
#define Tv 512
#define Hv 512
#define NLAYER 3
#define CPL 16
#define NCTA 96
#define BLK 256
#define NTICK (Tv + 2)
#define KEXT 3072
#define KCH 128
#define NCHUNK (KEXT / KCH)   // 24
#define NTILE 128
#define APAD 8
#define AROW (KCH + APAD)     // 136 elems
#define A_ELEMS (64 * AROW)
#define STAGE_BYTES ((64 + 128) * AROW * 2)   // 52224
#define SMEM_TOTAL (512 + 3 * STAGE_BYTES)

__device__ __nv_bfloat16 g_B[NLAYER][CPL][NTILE][KEXT];
__device__ __nv_bfloat16 g_A[NLAYER][2][Bv][KEXT];
__device__ float g_hst[NLAYER][2][Bv * Hv];
__device__ unsigned g_count = 0;
__device__ unsigned g_phase = 0;

__device__ __forceinline__ uint32_t smem_u32(const void* p) {
    uint32_t a;
    asm("{ .reg .u64 t; cvta.to.shared.u64 t, %1; cvt.u32.u64 %0, t; }" : "=r"(a) : "l"(p));
    return a;
}
__device__ __forceinline__ void cp16(uint32_t s, const void* g) {
    asm volatile("cp.async.cg.shared.global [%0], [%1], 16;" :: "r"(s), "l"(g));
}
__device__ __forceinline__ float sigf(float x) { return 1.f / (1.f + __expf(-x)); }
__device__ __forceinline__ float tanh_fast(float x) {
    x = fminf(fmaxf(x, -15.f), 15.f);
    float t = __expf(2.f * x);
    return (t - 1.f) / (t + 1.f);
}
__device__ __forceinline__ void gsync(unsigned target) {
    __syncthreads();
    if (threadIdx.x == 0) {
        __threadfence();
        unsigned a = atomicAdd(&g_count, 1u);
        if (a == NCTA - 1) {
            g_count = 0u;
            __threadfence();
            atomicAdd(&g_phase, 1u);
        } else {
            while (*((volatile unsigned*)&g_phase) < target) __nanosleep(32);
        }
    }
    __syncthreads();
}

#define MMA16816(d, a, b) \
    asm volatile("mma.sync.aligned.m16n8k16.row.col.f32.bf16.bf16.f32 " \
        "{%0,%1,%2,%3}, {%4,%5,%6,%7}, {%8,%9}, {%0,%1,%2,%3};" \
        : "+f"((d)[0]), "+f"((d)[1]), "+f"((d)[2]), "+f"((d)[3]) \
        : "r"((a)[0]), "r"((a)[1]), "r"((a)[2]), "r"((a)[3]), \
          "r"((b)[0]), "r"((b)[1]))

// ---------------- prep: permuted 3-region weights + state init ----------------
__global__ void gru_prep(const float* __restrict__ x,
    const float* __restrict__ Wih0, const float* __restrict__ Whh0,
    const float* __restrict__ Wih1, const float* __restrict__ Whh1,
    const float* __restrict__ Wih2, const float* __restrict__ Whh2)
{
    const float* WI[3] = {Wih0, Wih1, Wih2};
    const float* WH[3] = {Whh0, Whh1, Whh2};
    const long gsz = (long)gridDim.x * blockDim.x;
    const long gid = (long)blockIdx.x * blockDim.x + threadIdx.x;

    // B: [l][cta][n=gate*32+u][k], k: region = k/1024 (0,1 -> w_hi; 2 -> w_lo),
    // half = (k%1024)/512 (0 = x, 1 = h), kk = k%512.
    const long BTOT = (long)NLAYER * CPL * NTILE * KEXT;
    for (long idx = gid; idx < BTOT; idx += gsz) {
        int k   = (int)(idx % KEXT);
        long r0 = idx / KEXT;
        int n   = (int)(r0 % NTILE);
        long r1 = r0 / NTILE;
        int cta = (int)(r1 % CPL);
        int l   = (int)(r1 / CPL);
        int gate = n >> 5, u = n & 31, j = cta * 32 + u;
        int region = k >> 10, half = (k >> 9) & 1, kk = k & 511;
        float wv = 0.f;
        if (half == 0) {                       // x-half: r,z,i_n from W_ih
            if (gate < 3) wv = WI[l][(size_t)(gate * Hv + j) * Hv + kk];
        } else {                               // h-half: r,z from W_hh 0,1; h_n row 2
            if (gate == 0)      wv = WH[l][(size_t)(0 * Hv + j) * Hv + kk];
            else if (gate == 1) wv = WH[l][(size_t)(1 * Hv + j) * Hv + kk];
            else if (gate == 3) wv = WH[l][(size_t)(2 * Hv + j) * Hv + kk];
        }
        __nv_bfloat16 hi = __float2bfloat16(wv);
        __nv_bfloat16 out = (region < 2) ? hi
                          : __float2bfloat16(wv - __bfloat162float(hi));
        (&g_B[0][0][0][0])[idx] = out;
    }
    // A: region 0 = a_hi, 1 = a_lo, 2 = a_hi dup; init zeros except layer0
    // parity1 x-part = x_{t=0}.
    const long ATOT = (long)NLAYER * 2 * Bv * KEXT;
    for (long idx = gid; idx < ATOT; idx += gsz) {
        int k = (int)(idx % KEXT);
        long r0 = idx / KEXT;
        int m = (int)(r0 % Bv);
        long r1 = r0 / Bv;
        int p = (int)(r1 & 1);
        int l = (int)(r1 >> 1);
        __nv_bfloat16 out = __float2bfloat16(0.f);
        if (l == 0 && p == 1) {
            int region = k >> 10, half = (k >> 9) & 1, kk = k & 511;
            if (half == 0) {
                float v = x[((size_t)m * Tv) * Hv + kk];
                __nv_bfloat16 hi = __float2bfloat16(v);
                out = (region != 1) ? hi
                    : __float2bfloat16(v - __bfloat162float(hi));
            }
        }
        (&g_A[0][0][0][0])[idx] = out;
    }
    for (long idx = gid; idx < (long)NLAYER * 2 * Bv * Hv; idx += gsz)
        (&g_hst[0][0][0])[idx] = 0.f;
}

// ---------------- main persistent HMMA kernel ----------------
__global__ void __launch_bounds__(BLK, 1) gru_tc(
    const float* __restrict__ x,
    const float* __restrict__ bih0, const float* __restrict__ bhh0,
    const float* __restrict__ bih1, const float* __restrict__ bhh1,
    const float* __restrict__ bih2, const float* __restrict__ bhh2,
    float* __restrict__ y)
{
    extern __shared__ char smem[];
    const uint32_t sm0 = smem_u32(smem) + 512;
    const int tid  = threadIdx.x;
    const int lane = tid & 31;
    const int wid  = tid >> 5;
    const int mw   = wid >> 2;
    const int nw   = wid & 3;
    const int l     = blockIdx.x >> 5;
    const int li    = (blockIdx.x >> 1) & 15;
    const int mhalf = blockIdx.x & 1;
    const int J0    = li * 32;

    const float* bihL = (l == 0) ? bih0 : (l == 1) ? bih1 : bih2;
    const float* bhhL = (l == 0) ? bhh0 : (l == 1) ? bhh1 : bhh2;

    float* sb = (float*)smem;
    if (tid < 32) {
        int j = J0 + tid;
        sb[tid]      = bihL[0 * Hv + j] + bhhL[0 * Hv + j];
        sb[32 + tid] = bihL[1 * Hv + j] + bhhL[1 * Hv + j];
        sb[64 + tid] = bihL[2 * Hv + j];
        sb[96 + tid] = bhhL[2 * Hv + j];
    }
    __syncthreads();

    const __nv_bfloat16* Bg = &g_B[l][li][0][0];
    const unsigned base = *((volatile unsigned*)&g_phase);

#pragma unroll 1
    for (int k = 0; k < NTICK; ++k) {
        const int t = k - l;
        const bool active = (t >= 0) && (t < Tv);
        const int rp = (k + 1) & 1;
        const int wp = k & 1;

        if (active) {
            const __nv_bfloat16* Ag = &g_A[l][rp][64 * mhalf][0];

            auto stage = [&](int s) {
                uint32_t buf = sm0 + (uint32_t)(s % 3) * STAGE_BYTES;
                const char* gaB = (const char*)Ag + (size_t)s * (KCH * 2);
                const char* gbB = (const char*)Bg + (size_t)s * (KCH * 2);
#pragma unroll
                for (int i2 = 0; i2 < 4; ++i2) {       // A: 64 rows x 16 x 16B
                    int i = tid + i2 * BLK;
                    int r = i >> 4, c16 = i & 15;
                    cp16(buf + (uint32_t)(r * (AROW * 2) + c16 * 16),
                         gaB + (size_t)r * (KEXT * 2) + c16 * 16);
                }
                uint32_t bufB = buf + A_ELEMS * 2;
#pragma unroll
                for (int i2 = 0; i2 < 8; ++i2) {       // B: 128 rows x 16 x 16B
                    int i = tid + i2 * BLK;
                    int r = i >> 4, c16 = i & 15;
                    cp16(bufB + (uint32_t)(r * (AROW * 2) + c16 * 16),
                         gbB + (size_t)r * (KEXT * 2) + c16 * 16);
                }
                asm volatile("cp.async.commit_group;");
            };

            float acc[2][4][4];
#pragma unroll
            for (int mt = 0; mt < 2; ++mt)
#pragma unroll
                for (int g = 0; g < 4; ++g)
#pragma unroll
                    for (int e = 0; e < 4; ++e) acc[mt][g][e] = 0.f;

            stage(0); stage(1);
#pragma unroll 1
            for (int c = 0; c < NCHUNK; ++c) {
                if (c < NCHUNK - 1) asm volatile("cp.async.wait_group 1;");
                else                asm volatile("cp.async.wait_group 0;");
                __syncthreads();
                if (c + 2 < NCHUNK) stage(c + 2);

                const __nv_bfloat16* As =
                    (const __nv_bfloat16*)(smem + 512 + (size_t)(c % 3) * STAGE_BYTES);
                const __nv_bfloat16* Bs = As + A_ELEMS;
                const int lq = lane >> 2, lr2 = (lane & 3) * 2;
#pragma unroll
                for (int ks = 0; ks < KCH / 16; ++ks) {
                    const int kk = ks * 16 + lr2;
                    uint32_t a[2][4];
#pragma unroll
                    for (int mt = 0; mt < 2; ++mt) {
                        const __nv_bfloat16* ab = As + (32 * mw + 16 * mt + lq) * AROW + kk;
                        a[mt][0] = *(const uint32_t*)(ab);
                        a[mt][1] = *(const uint32_t*)(ab + 8 * AROW);
                        a[mt][2] = *(const uint32_t*)(ab + 8);
                        a[mt][3] = *(const uint32_t*)(ab + 8 * AROW + 8);
                    }
#pragma unroll
                    for (int g = 0; g < 4; ++g) {
                        const __nv_bfloat16* bb = Bs + (32 * g + 8 * nw + lq) * AROW + kk;
                        uint32_t b[2];
                        b[0] = *(const uint32_t*)(bb);
                        b[1] = *(const uint32_t*)(bb + 8);
#pragma unroll
                        for (int mt = 0; mt < 2; ++mt)
                            MMA16816(acc[mt][g], a[mt], b);
                    }
                }
            }

            // ---------- epilogue ----------
            const float* hrd = g_hst[l][rp];
            float*       hwr = g_hst[l][wp];
            __nv_bfloat16* AwS = &g_A[l][wp][0][0];
            __nv_bfloat16* AwN = (l < 2) ? &g_A[l + 1][wp][0][0] : (__nv_bfloat16*)0;
            const int u0 = 8 * nw + (lane & 3) * 2;

#pragma unroll
            for (int mt = 0; mt < 2; ++mt) {
#pragma unroll
                for (int rr = 0; rr < 2; ++rr) {
                    const int m = 64 * mhalf + 32 * mw + 16 * mt + (lane >> 2) + 8 * rr;
                    float hv[2];
#pragma unroll
                    for (int up = 0; up < 2; ++up) {
                        const int u = u0 + up, e = 2 * rr + up;
                        float r = sigf(acc[mt][0][e] + sb[u]);
                        float z = sigf(acc[mt][1][e] + sb[32 + u]);
                        float n = tanh_fast(acc[mt][2][e] + sb[64 + u]
                                            + r * (acc[mt][3][e] + sb[96 + u]));
                        float hp = hrd[(size_t)m * Hv + J0 + u];
                        hv[up] = (1.f - z) * n + z * hp;
                    }
                    const int j0 = J0 + u0;
                    if (l == 2) {
                        float2 xv = *(const float2*)(x + ((size_t)m * Tv + t) * Hv + j0);
                        if (xv.x == 0.f) hv[0] = 0.f;
                        if (xv.y == 0.f) hv[1] = 0.f;
                        *(float2*)(y + ((size_t)m * Tv + t) * Hv + j0) =
                            make_float2(hv[0], hv[1]);
                    }
                    *(float2*)(hwr + (size_t)m * Hv + j0) = make_float2(hv[0], hv[1]);

                    __nv_bfloat16 h0 = __float2bfloat16(hv[0]);
                    __nv_bfloat16 h1 = __float2bfloat16(hv[1]);
                    __nv_bfloat16 L0 = __float2bfloat16(hv[0] - __bfloat162float(h0));
                    __nv_bfloat16 L1 = __float2bfloat16(hv[1] - __bfloat162float(h1));
                    unsigned hp32 = (unsigned)__bfloat16_as_ushort(h0)
                                  | ((unsigned)__bfloat16_as_ushort(h1) << 16);
                    unsigned lp32 = (unsigned)__bfloat16_as_ushort(L0)
                                  | ((unsigned)__bfloat16_as_ushort(L1) << 16);
                    // self (h-half): hi @512+j0, lo @1536+j0, hi dup @2560+j0
                    __nv_bfloat16* pS = AwS + (size_t)m * KEXT + 512 + j0;
                    *(unsigned*)pS = hp32;
                    *(unsigned*)(pS + 1024) = lp32;
                    *(unsigned*)(pS + 2048) = hp32;
                    if (l < 2) {   // next layer (x-half): hi @j0, lo @1024+j0, hi dup @2048+j0
                        __nv_bfloat16* pN = AwN + (size_t)m * KEXT + j0;
                        *(unsigned*)pN = hp32;
                        *(unsigned*)(pN + 1024) = lp32;
                        *(unsigned*)(pN + 2048) = hp32;
                    }
                }
            }
        }

        // layer-0 CTAs stage x_{k+1} into next parity's A0 x-region
        if (l == 0 && (k + 1) < Tv) {
            const int row = tid >> 2;
            const int kc0 = (tid & 3) * 8;
            const int m = 64 * mhalf + row;
            const float* xs = x + ((size_t)m * Tv + (k + 1)) * Hv + 32 * li + kc0;
            unsigned hp[4], lp[4];
#pragma unroll
            for (int q = 0; q < 4; ++q) {
                float v0 = xs[2 * q], v1 = xs[2 * q + 1];
                __nv_bfloat16 h0 = __float2bfloat16(v0);
                __nv_bfloat16 h1 = __float2bfloat16(v1);
                __nv_bfloat16 L0 = __float2bfloat16(v0 - __bfloat162float(h0));
                __nv_bfloat16 L1 = __float2bfloat16(v1 - __bfloat162float(h1));
                hp[q] = (unsigned)__bfloat16_as_ushort(h0)
                      | ((unsigned)__bfloat16_as_ushort(h1) << 16);
                lp[q] = (unsigned)__bfloat16_as_ushort(L0)
                      | ((unsigned)__bfloat16_as_ushort(L1) << 16);
            }
            __nv_bfloat16* d0 = &g_A[0][wp][m][32 * li + kc0];
            *(uint4*)d0 = make_uint4(hp[0], hp[1], hp[2], hp[3]);
            *(uint4*)(d0 + 1024) = make_uint4(lp[0], lp[1], lp[2], lp[3]);
            *(uint4*)(d0 + 2048) = make_uint4(hp[0], hp[1], hp[2], hp[3]);
        }

        gsync(base + 1 + k);
    }
}

extern "C" void kernel_launch(void* const* d_in, const int* in_sizes, int n_in,
                              void* d_out, int out_size) {
    (void)in_sizes; (void)n_in; (void)out_size;
    const float* x = (const float*)d_in[0];
    gru_prep<<<256, 256>>>(x,
        (const float*)d_in[1], (const float*)d_in[2],
        (const float*)d_in[5], (const float*)d_in[6],
        (const float*)d_in[9], (const float*)d_in[10]);
    cudaFuncSetAttribute(gru_tc, cudaFuncAttributeMaxDynamicSharedMemorySize, SMEM_TOTAL);
    gru_tc<<<NCTA, BLK, SMEM_TOTAL>>>(x,
        (const float*)d_in[3],  (const float*)d_in[4],
        (const float*)d_in[7],  (const float*)d_in[8],
        (const float*)d_in[11], (const float*)d_in[12],
        (float*)d_out);
}

// round 8
// speedup vs baseline: 5.9201x; 1.2538x over previous
#include <cuda_runtime.h>
#include <cuda_bf16.h>
#include <cstdint>

// 3-layer GRU (r,z,n), B=128, T=512, H=512, fp32 — bf16 hi/lo mma.sync, v2.
// Wavefront: tick k -> layer l computes t = k - l; one grid barrier per tick.
// 96 CTAs = 3 layers x 16 col-tiles (32 units) x 2 batch halves; 8 warps.
// Per tick each CTA: D[64,128] = sum over real K=1024 of
//   a_hi*w_hi + a_lo*w_hi + a_hi*w_lo   (compensated bf16 product, ~2^-16 rel)
// staged per 64-wide K chunk as 4 unique planes {a_hi,a_lo,w_hi,w_lo} in a
// 3-stage cp.async ring; fragments via ldmatrix.x4; 24 MMA per warp per ks.
// Columns: [r(32), z(32), i_n(32), h_n(32)] (prep-permuted weights; i_n zero in
// h-half, h_n zero in x-half). K layout: [x 512 | h 512].

#define Bv 128
#define Tv 512
#define Hv 512
#define NLAYER 3
#define CPL 16
#define NCTA 96
#define BLK 256
#define NTICK (Tv + 2)
#define KREAL 1024
#define KCH 64
#define NCHUNK (KREAL / KCH)   // 16
#define AROWB 144              // (KCH+8)*2 bytes per smem row
#define OFF_AHI 0
#define OFF_ALO 9216           // 64*144
#define OFF_WHI 18432
#define OFF_WLO 36864          // 18432 + 128*144
#define STAGE_BYTES 55296      // 36864 + 128*144
#define SMEM_TOTAL (512 + 3 * STAGE_BYTES)

__device__ __nv_bfloat16 g_B[NLAYER][CPL][2][128][KREAL];  // [hl][n][k]
__device__ __nv_bfloat16 g_A[NLAYER][2][2][Bv][KREAL];     // [parity][hl][m][k]
__device__ float g_hst[NLAYER][2][Bv * Hv];
__device__ unsigned g_count = 0;
__device__ unsigned g_phase = 0;

__device__ __forceinline__ uint32_t smem_u32(const void* p) {
    uint32_t a;
    asm("{ .reg .u64 t; cvta.to.shared.u64 t, %1; cvt.u32.u64 %0, t; }" : "=r"(a) : "l"(p));
    return a;
}
__device__ __forceinline__ void cp16(uint32_t s, const void* g) {
    asm volatile("cp.async.cg.shared.global [%0], [%1], 16;" :: "r"(s), "l"(g));
}
__device__ __forceinline__ float sigf(float x) { return 1.f / (1.f + __expf(-x)); }
__device__ __forceinline__ float tanh_fast(float x) {
    x = fminf(fmaxf(x, -15.f), 15.f);
    float t = __expf(2.f * x);
    return (t - 1.f) / (t + 1.f);
}
__device__ __forceinline__ void gsync(unsigned target) {
    __syncthreads();
    if (threadIdx.x == 0) {
        __threadfence();
        unsigned a = atomicAdd(&g_count, 1u);
        if (a == NCTA - 1) {
            g_count = 0u;
            __threadfence();
            atomicAdd(&g_phase, 1u);
        } else {
            while (*((volatile unsigned*)&g_phase) < target) __nanosleep(32);
        }
    }
    __syncthreads();
}

#define MMA16816(d, a, b0, b1) \
    asm volatile("mma.sync.aligned.m16n8k16.row.col.f32.bf16.bf16.f32 " \
        "{%0,%1,%2,%3}, {%4,%5,%6,%7}, {%8,%9}, {%0,%1,%2,%3};" \
        : "+f"((d)[0]), "+f"((d)[1]), "+f"((d)[2]), "+f"((d)[3]) \
        : "r"((a)[0]), "r"((a)[1]), "r"((a)[2]), "r"((a)[3]), \
          "r"(b0), "r"(b1))

#define LDMX4(r, a) \
    asm volatile("ldmatrix.sync.aligned.m8n8.x4.shared.b16 {%0,%1,%2,%3}, [%4];" \
        : "=r"((r)[0]), "=r"((r)[1]), "=r"((r)[2]), "=r"((r)[3]) : "r"(a))

// ---------------- prep: permuted hi/lo weights + state init ----------------
__global__ void gru_prep(const float* __restrict__ x,
    const float* __restrict__ Wih0, const float* __restrict__ Whh0,
    const float* __restrict__ Wih1, const float* __restrict__ Whh1,
    const float* __restrict__ Wih2, const float* __restrict__ Whh2)
{
    const float* WI[3] = {Wih0, Wih1, Wih2};
    const float* WH[3] = {Whh0, Whh1, Whh2};
    const long gsz = (long)gridDim.x * blockDim.x;
    const long gid = (long)blockIdx.x * blockDim.x + threadIdx.x;

    // B: [l][li][hl][n=gate*32+u][k], k: half = k/512 (0=x,1=h), kk = k%512.
    const long BTOT = (long)NLAYER * CPL * 2 * 128 * KREAL;
    for (long idx = gid; idx < BTOT; idx += gsz) {
        int k   = (int)(idx & (KREAL - 1));
        long r0 = idx >> 10;
        int n   = (int)(r0 & 127);
        long r1 = r0 >> 7;
        int hl  = (int)(r1 & 1);
        long r2 = r1 >> 1;
        int li  = (int)(r2 % CPL);
        int l   = (int)(r2 / CPL);
        int gate = n >> 5, u = n & 31, j = li * 32 + u;
        int half = k >> 9, kk = k & 511;
        float wv = 0.f;
        if (half == 0) {                       // x-half: r,z,i_n from W_ih
            if (gate < 3) wv = WI[l][(size_t)(gate * Hv + j) * Hv + kk];
        } else {                               // h-half: r,z from W_hh 0,1; h_n row 2
            if (gate == 0)      wv = WH[l][(size_t)(0 * Hv + j) * Hv + kk];
            else if (gate == 1) wv = WH[l][(size_t)(1 * Hv + j) * Hv + kk];
            else if (gate == 3) wv = WH[l][(size_t)(2 * Hv + j) * Hv + kk];
        }
        __nv_bfloat16 hi = __float2bfloat16(wv);
        (&g_B[0][0][0][0][0])[idx] = (hl == 0) ? hi
            : __float2bfloat16(wv - __bfloat162float(hi));
    }
    // A: [l][p][hl][m][k]; zeros except layer0 parity1 x-part = x_{t=0}.
    const long ATOT = (long)NLAYER * 2 * 2 * Bv * KREAL;
    for (long idx = gid; idx < ATOT; idx += gsz) {
        int k = (int)(idx & (KREAL - 1));
        long r0 = idx >> 10;
        int m = (int)(r0 & 127);
        long r1 = r0 >> 7;
        int hl = (int)(r1 & 1);
        int p  = (int)((r1 >> 1) & 1);
        int l  = (int)(r1 >> 2);
        __nv_bfloat16 out = __float2bfloat16(0.f);
        if (l == 0 && p == 1 && k < 512) {
            float v = x[((size_t)m * Tv) * Hv + k];
            __nv_bfloat16 hi = __float2bfloat16(v);
            out = (hl == 0) ? hi : __float2bfloat16(v - __bfloat162float(hi));
        }
        (&g_A[0][0][0][0][0])[idx] = out;
    }
    for (long idx = gid; idx < (long)NLAYER * 2 * Bv * Hv; idx += gsz)
        (&g_hst[0][0][0])[idx] = 0.f;
}

// ---------------- main persistent HMMA kernel ----------------
__global__ void __launch_bounds__(BLK, 1) gru_tc(
    const float* __restrict__ x,
    const float* __restrict__ bih0, const float* __restrict__ bhh0,
    const float* __restrict__ bih1, const float* __restrict__ bhh1,
    const float* __restrict__ bih2, const float* __restrict__ bhh2,
    float* __restrict__ y)
{
    extern __shared__ char smem[];
    const uint32_t sm0 = smem_u32(smem) + 512;
    const int tid  = threadIdx.x;
    const int lane = tid & 31;
    const int wid  = tid >> 5;
    const int mw   = wid >> 2;          // 0,1: 32-row M tile within CTA half
    const int nw   = wid & 3;           // 0..3: 8-unit group
    const int l     = blockIdx.x >> 5;
    const int li    = (blockIdx.x >> 1) & 15;
    const int mhalf = blockIdx.x & 1;
    const int J0    = li * 32;

    const float* bihL = (l == 0) ? bih0 : (l == 1) ? bih1 : bih2;
    const float* bhhL = (l == 0) ? bhh0 : (l == 1) ? bhh1 : bhh2;

    float* sb = (float*)smem;           // br+bz pre-added, bni, bnh
    if (tid < 32) {
        int j = J0 + tid;
        sb[tid]      = bihL[0 * Hv + j] + bhhL[0 * Hv + j];
        sb[32 + tid] = bihL[1 * Hv + j] + bhhL[1 * Hv + j];
        sb[64 + tid] = bihL[2 * Hv + j];
        sb[96 + tid] = bhhL[2 * Hv + j];
    }
    __syncthreads();

    // ldmatrix per-lane offsets (bytes within a stage).
    const uint32_t aoff = (uint32_t)((32 * mw + (lane & 15)) * AROWB + (lane >> 4) * 16);
    const uint32_t boff0 = (uint32_t)((32 * (lane >> 4) + 8 * nw + (lane & 7)) * AROWB
                                      + ((lane >> 3) & 1) * 16);
    const uint32_t boff1 = boff0 + 64u * AROWB;

    const __nv_bfloat16* Bg = &g_B[l][li][0][0][0];
    const unsigned base = *((volatile unsigned*)&g_phase);

#pragma unroll 1
    for (int k = 0; k < NTICK; ++k) {
        const int t = k - l;
        const bool active = (t >= 0) && (t < Tv);
        const int rp = (k + 1) & 1;
        const int wp = k & 1;

        if (active) {
            const __nv_bfloat16* Ag = &g_A[l][rp][0][0][0];

            auto stage = [&](int s) {
                uint32_t buf = sm0 + (uint32_t)(s % 3) * STAGE_BYTES;
                const char* gaB = (const char*)Ag + (size_t)s * (KCH * 2);
                const char* gbB = (const char*)Bg + (size_t)s * (KCH * 2);
#pragma unroll
                for (int i2 = 0; i2 < 12; ++i2) {
                    int i = tid + i2 * BLK;          // 0..3071
                    int c16 = i & 7;
                    int rl = i >> 3;                 // 0..383
                    uint32_t dst; const char* src;
                    if (rl < 128) {                  // A planes (hi, lo), 64 rows each
                        int hl = rl >> 6, r = rl & 63;
                        dst = buf + (uint32_t)(hl * OFF_ALO + r * AROWB + c16 * 16);
                        src = gaB + ((size_t)hl * 128 + 64 * mhalf + r) * (KREAL * 2)
                                  + c16 * 16;
                    } else {                         // W planes (hi, lo), 128 rows each
                        int rb = rl - 128;
                        int hl = rb >> 7, r = rb & 127;
                        dst = buf + (uint32_t)(OFF_WHI + hl * 18432 + r * AROWB + c16 * 16);
                        src = gbB + ((size_t)hl * 128 + r) * (KREAL * 2) + c16 * 16;
                    }
                    cp16(dst, src);
                }
                asm volatile("cp.async.commit_group;");
            };

            float acc[2][4][4];
#pragma unroll
            for (int mt = 0; mt < 2; ++mt)
#pragma unroll
                for (int g = 0; g < 4; ++g)
#pragma unroll
                    for (int e = 0; e < 4; ++e) acc[mt][g][e] = 0.f;

            stage(0); stage(1);
#pragma unroll 1
            for (int c = 0; c < NCHUNK; ++c) {
                if (c < NCHUNK - 1) asm volatile("cp.async.wait_group 1;");
                else                asm volatile("cp.async.wait_group 0;");
                __syncthreads();
                if (c + 2 < NCHUNK) stage(c + 2);

                const uint32_t st = sm0 + (uint32_t)(c % 3) * STAGE_BYTES;
#pragma unroll
                for (int ks = 0; ks < KCH / 16; ++ks) {
                    const uint32_t kb = (uint32_t)(ks * 32);
                    uint32_t ahi[2][4], alo[2][4];
                    LDMX4(ahi[0], st + OFF_AHI + aoff + kb);
                    LDMX4(ahi[1], st + OFF_AHI + aoff + 16u * AROWB + kb);
                    LDMX4(alo[0], st + OFF_ALO + aoff + kb);
                    LDMX4(alo[1], st + OFF_ALO + aoff + 16u * AROWB + kb);
                    uint32_t wh0[4], wh1[4], wl0[4], wl1[4];
                    LDMX4(wh0, st + OFF_WHI + boff0 + kb);
                    LDMX4(wh1, st + OFF_WHI + boff1 + kb);
                    LDMX4(wl0, st + OFF_WLO + boff0 + kb);
                    LDMX4(wl1, st + OFF_WLO + boff1 + kb);
#pragma unroll
                    for (int mt = 0; mt < 2; ++mt) {
                        MMA16816(acc[mt][0], ahi[mt], wh0[0], wh0[1]);
                        MMA16816(acc[mt][1], ahi[mt], wh0[2], wh0[3]);
                        MMA16816(acc[mt][2], ahi[mt], wh1[0], wh1[1]);
                        MMA16816(acc[mt][3], ahi[mt], wh1[2], wh1[3]);
                        MMA16816(acc[mt][0], alo[mt], wh0[0], wh0[1]);
                        MMA16816(acc[mt][1], alo[mt], wh0[2], wh0[3]);
                        MMA16816(acc[mt][2], alo[mt], wh1[0], wh1[1]);
                        MMA16816(acc[mt][3], alo[mt], wh1[2], wh1[3]);
                        MMA16816(acc[mt][0], ahi[mt], wl0[0], wl0[1]);
                        MMA16816(acc[mt][1], ahi[mt], wl0[2], wl0[3]);
                        MMA16816(acc[mt][2], ahi[mt], wl1[0], wl1[1]);
                        MMA16816(acc[mt][3], ahi[mt], wl1[2], wl1[3]);
                    }
                }
            }

            // ---------- epilogue ----------
            const float* hrd = g_hst[l][rp];
            float*       hwr = g_hst[l][wp];
            const int u0 = 8 * nw + (lane & 3) * 2;

#pragma unroll
            for (int mt = 0; mt < 2; ++mt) {
#pragma unroll
                for (int rr = 0; rr < 2; ++rr) {
                    const int m = 64 * mhalf + 32 * mw + 16 * mt + (lane >> 2) + 8 * rr;
                    float hv[2];
#pragma unroll
                    for (int up = 0; up < 2; ++up) {
                        const int u = u0 + up, e = 2 * rr + up;
                        float r = sigf(acc[mt][0][e] + sb[u]);
                        float z = sigf(acc[mt][1][e] + sb[32 + u]);
                        float n = tanh_fast(acc[mt][2][e] + sb[64 + u]
                                            + r * (acc[mt][3][e] + sb[96 + u]));
                        float hp = hrd[(size_t)m * Hv + J0 + u];
                        hv[up] = (1.f - z) * n + z * hp;
                    }
                    const int j0 = J0 + u0;
                    if (l == 2) {
                        float2 xv = *(const float2*)(x + ((size_t)m * Tv + t) * Hv + j0);
                        if (xv.x == 0.f) hv[0] = 0.f;
                        if (xv.y == 0.f) hv[1] = 0.f;
                        *(float2*)(y + ((size_t)m * Tv + t) * Hv + j0) =
                            make_float2(hv[0], hv[1]);
                    }
                    *(float2*)(hwr + (size_t)m * Hv + j0) = make_float2(hv[0], hv[1]);

                    __nv_bfloat16 h0 = __float2bfloat16(hv[0]);
                    __nv_bfloat16 h1 = __float2bfloat16(hv[1]);
                    __nv_bfloat16 L0 = __float2bfloat16(hv[0] - __bfloat162float(h0));
                    __nv_bfloat16 L1 = __float2bfloat16(hv[1] - __bfloat162float(h1));
                    unsigned hp32 = (unsigned)__bfloat16_as_ushort(h0)
                                  | ((unsigned)__bfloat16_as_ushort(h1) << 16);
                    unsigned lp32 = (unsigned)__bfloat16_as_ushort(L0)
                                  | ((unsigned)__bfloat16_as_ushort(L1) << 16);
                    *(unsigned*)&g_A[l][wp][0][m][512 + j0] = hp32;   // self h-half
                    *(unsigned*)&g_A[l][wp][1][m][512 + j0] = lp32;
                    if (l < 2) {                                      // next-layer x-half
                        *(unsigned*)&g_A[l + 1][wp][0][m][j0] = hp32;
                        *(unsigned*)&g_A[l + 1][wp][1][m][j0] = lp32;
                    }
                }
            }
        }

        // layer-0 CTAs stage x_{k+1} into next parity's A0 x-region
        if (l == 0 && (k + 1) < Tv) {
            const int row = tid >> 2;
            const int kc0 = (tid & 3) * 8;
            const int m = 64 * mhalf + row;
            const float* xs = x + ((size_t)m * Tv + (k + 1)) * Hv + 32 * li + kc0;
            unsigned hp[4], lp[4];
#pragma unroll
            for (int q = 0; q < 4; ++q) {
                float v0 = xs[2 * q], v1 = xs[2 * q + 1];
                __nv_bfloat16 h0 = __float2bfloat16(v0);
                __nv_bfloat16 h1 = __float2bfloat16(v1);
                __nv_bfloat16 L0 = __float2bfloat16(v0 - __bfloat162float(h0));
                __nv_bfloat16 L1 = __float2bfloat16(v1 - __bfloat162float(h1));
                hp[q] = (unsigned)__bfloat16_as_ushort(h0)
                      | ((unsigned)__bfloat16_as_ushort(h1) << 16);
                lp[q] = (unsigned)__bfloat16_as_ushort(L0)
                      | ((unsigned)__bfloat16_as_ushort(L1) << 16);
            }
            *(uint4*)&g_A[0][wp][0][m][32 * li + kc0] =
                make_uint4(hp[0], hp[1], hp[2], hp[3]);
            *(uint4*)&g_A[0][wp][1][m][32 * li + kc0] =
                make_uint4(lp[0], lp[1], lp[2], lp[3]);
        }

        gsync(base + 1 + k);
    }
}

extern "C" void kernel_launch(void* const* d_in, const int* in_sizes, int n_in,
                              void* d_out, int out_size) {
    (void)in_sizes; (void)n_in; (void)out_size;
    const float* x = (const float*)d_in[0];
    gru_prep<<<256, 256>>>(x,
        (const float*)d_in[1], (const float*)d_in[2],
        (const float*)d_in[5], (const float*)d_in[6],
        (const float*)d_in[9], (const float*)d_in[10]);
    cudaFuncSetAttribute(gru_tc, cudaFuncAttributeMaxDynamicSharedMemorySize, SMEM_TOTAL);
    gru_tc<<<NCTA, BLK, SMEM_TOTAL>>>(x,
        (const float*)d_in[3],  (const float*)d_in[4],
        (const float*)d_in[7],  (const float*)d_in[8],
        (const float*)d_in[11], (const float*)d_in[12],
        (float*)d_out);
}

// round 9
// speedup vs baseline: 5.9917x; 1.0121x over previous
#include <cuda_runtime.h>
#include <cuda_bf16.h>
#include <cstdint>

// 3-layer GRU (r,z,n), B=128, T=512, H=512, fp32 — bf16 hi/lo mma.sync, v3.
// Wavefront: tick k -> layer l computes t = k - l; one grid barrier per tick.
// 96 CTAs = 3 layers x 16 col-tiles (32 units) x 2 batch halves; NOW 16 warps
// (4 M-warps x 4 N-warps, warp tile D[16,128]) for 4 warps/SMSP latency hiding.
// Per tick each CTA: D[64,128] = sum over real K=1024 of
//   a_hi*w_hi + a_lo*w_hi + a_hi*w_lo   (compensated bf16 product, ~2^-16 rel)
// staged per 64-wide K chunk as 4 unique planes {a_hi,a_lo,w_hi,w_lo} in a
// 3-stage cp.async ring; fragments via ldmatrix.x4; 12 MMA per warp per ks.
// Columns: [r(32), z(32), i_n(32), h_n(32)] (prep-permuted weights).

#define Bv 128
#define Tv 512
#define Hv 512
#define NLAYER 3
#define CPL 16
#define NCTA 96
#define BLK 512
#define NTICK (Tv + 2)
#define KREAL 1024
#define KCH 64
#define NCHUNK (KREAL / KCH)   // 16
#define AROWB 144              // (KCH+8)*2 bytes per smem row
#define OFF_AHI 0
#define OFF_ALO 9216           // 64*144
#define OFF_WHI 18432
#define OFF_WLO 36864          // 18432 + 128*144
#define STAGE_BYTES 55296      // 36864 + 128*144
#define SMEM_TOTAL (512 + 3 * STAGE_BYTES)

__device__ __nv_bfloat16 g_B[NLAYER][CPL][2][128][KREAL];  // [hl][n][k]
__device__ __nv_bfloat16 g_A[NLAYER][2][2][Bv][KREAL];     // [parity][hl][m][k]
__device__ float g_hst[NLAYER][2][Bv * Hv];
__device__ unsigned g_count = 0;
__device__ unsigned g_phase = 0;

__device__ __forceinline__ uint32_t smem_u32(const void* p) {
    uint32_t a;
    asm("{ .reg .u64 t; cvta.to.shared.u64 t, %1; cvt.u32.u64 %0, t; }" : "=r"(a) : "l"(p));
    return a;
}
__device__ __forceinline__ void cp16(uint32_t s, const void* g) {
    asm volatile("cp.async.cg.shared.global [%0], [%1], 16;" :: "r"(s), "l"(g));
}
__device__ __forceinline__ float sigf(float x) { return 1.f / (1.f + __expf(-x)); }
__device__ __forceinline__ float tanh_fast(float x) {
    x = fminf(fmaxf(x, -15.f), 15.f);
    float t = __expf(2.f * x);
    return (t - 1.f) / (t + 1.f);
}
__device__ __forceinline__ void gsync(unsigned target) {
    __syncthreads();
    if (threadIdx.x == 0) {
        __threadfence();
        unsigned a = atomicAdd(&g_count, 1u);
        if (a == NCTA - 1) {
            g_count = 0u;
            __threadfence();
            atomicAdd(&g_phase, 1u);
        } else {
            while (*((volatile unsigned*)&g_phase) < target) __nanosleep(32);
        }
    }
    __syncthreads();
}

#define MMA16816(d, a, b0, b1) \
    asm volatile("mma.sync.aligned.m16n8k16.row.col.f32.bf16.bf16.f32 " \
        "{%0,%1,%2,%3}, {%4,%5,%6,%7}, {%8,%9}, {%0,%1,%2,%3};" \
        : "+f"((d)[0]), "+f"((d)[1]), "+f"((d)[2]), "+f"((d)[3]) \
        : "r"((a)[0]), "r"((a)[1]), "r"((a)[2]), "r"((a)[3]), \
          "r"(b0), "r"(b1))

#define LDMX4(r, a) \
    asm volatile("ldmatrix.sync.aligned.m8n8.x4.shared.b16 {%0,%1,%2,%3}, [%4];" \
        : "=r"((r)[0]), "=r"((r)[1]), "=r"((r)[2]), "=r"((r)[3]) : "r"(a))

// ---------------- prep: permuted hi/lo weights + state init ----------------
__global__ void gru_prep(const float* __restrict__ x,
    const float* __restrict__ Wih0, const float* __restrict__ Whh0,
    const float* __restrict__ Wih1, const float* __restrict__ Whh1,
    const float* __restrict__ Wih2, const float* __restrict__ Whh2)
{
    const float* WI[3] = {Wih0, Wih1, Wih2};
    const float* WH[3] = {Whh0, Whh1, Whh2};
    const long gsz = (long)gridDim.x * blockDim.x;
    const long gid = (long)blockIdx.x * blockDim.x + threadIdx.x;

    const long BTOT = (long)NLAYER * CPL * 2 * 128 * KREAL;
    for (long idx = gid; idx < BTOT; idx += gsz) {
        int k   = (int)(idx & (KREAL - 1));
        long r0 = idx >> 10;
        int n   = (int)(r0 & 127);
        long r1 = r0 >> 7;
        int hl  = (int)(r1 & 1);
        long r2 = r1 >> 1;
        int li  = (int)(r2 % CPL);
        int l   = (int)(r2 / CPL);
        int gate = n >> 5, u = n & 31, j = li * 32 + u;
        int half = k >> 9, kk = k & 511;
        float wv = 0.f;
        if (half == 0) {
            if (gate < 3) wv = WI[l][(size_t)(gate * Hv + j) * Hv + kk];
        } else {
            if (gate == 0)      wv = WH[l][(size_t)(0 * Hv + j) * Hv + kk];
            else if (gate == 1) wv = WH[l][(size_t)(1 * Hv + j) * Hv + kk];
            else if (gate == 3) wv = WH[l][(size_t)(2 * Hv + j) * Hv + kk];
        }
        __nv_bfloat16 hi = __float2bfloat16(wv);
        (&g_B[0][0][0][0][0])[idx] = (hl == 0) ? hi
            : __float2bfloat16(wv - __bfloat162float(hi));
    }
    const long ATOT = (long)NLAYER * 2 * 2 * Bv * KREAL;
    for (long idx = gid; idx < ATOT; idx += gsz) {
        int k = (int)(idx & (KREAL - 1));
        long r0 = idx >> 10;
        int m = (int)(r0 & 127);
        long r1 = r0 >> 7;
        int hl = (int)(r1 & 1);
        int p  = (int)((r1 >> 1) & 1);
        int l  = (int)(r1 >> 2);
        __nv_bfloat16 out = __float2bfloat16(0.f);
        if (l == 0 && p == 1 && k < 512) {
            float v = x[((size_t)m * Tv) * Hv + k];
            __nv_bfloat16 hi = __float2bfloat16(v);
            out = (hl == 0) ? hi : __float2bfloat16(v - __bfloat162float(hi));
        }
        (&g_A[0][0][0][0][0])[idx] = out;
    }
    for (long idx = gid; idx < (long)NLAYER * 2 * Bv * Hv; idx += gsz)
        (&g_hst[0][0][0])[idx] = 0.f;
}

// ---------------- main persistent HMMA kernel ----------------
__global__ void __launch_bounds__(BLK, 1) gru_tc(
    const float* __restrict__ x,
    const float* __restrict__ bih0, const float* __restrict__ bhh0,
    const float* __restrict__ bih1, const float* __restrict__ bhh1,
    const float* __restrict__ bih2, const float* __restrict__ bhh2,
    float* __restrict__ y)
{
    extern __shared__ char smem[];
    const uint32_t sm0 = smem_u32(smem) + 512;
    const int tid  = threadIdx.x;
    const int lane = tid & 31;
    const int wid  = tid >> 5;
    const int mw   = wid >> 2;          // 0..3: 16-row M tile within CTA half
    const int nw   = wid & 3;           // 0..3: 8-unit group
    const int l     = blockIdx.x >> 5;
    const int li    = (blockIdx.x >> 1) & 15;
    const int mhalf = blockIdx.x & 1;
    const int J0    = li * 32;

    const float* bihL = (l == 0) ? bih0 : (l == 1) ? bih1 : bih2;
    const float* bhhL = (l == 0) ? bhh0 : (l == 1) ? bhh1 : bhh2;

    float* sb = (float*)smem;           // br+bz pre-added, bni, bnh
    if (tid < 32) {
        int j = J0 + tid;
        sb[tid]      = bihL[0 * Hv + j] + bhhL[0 * Hv + j];
        sb[32 + tid] = bihL[1 * Hv + j] + bhhL[1 * Hv + j];
        sb[64 + tid] = bihL[2 * Hv + j];
        sb[96 + tid] = bhhL[2 * Hv + j];
    }
    __syncthreads();

    // ldmatrix per-lane offsets (bytes within a stage).
    const uint32_t aoff = (uint32_t)((16 * mw + (lane & 15)) * AROWB + (lane >> 4) * 16);
    const uint32_t boff0 = (uint32_t)((32 * (lane >> 4) + 8 * nw + (lane & 7)) * AROWB
                                      + ((lane >> 3) & 1) * 16);
    const uint32_t boff1 = boff0 + 64u * AROWB;

    const __nv_bfloat16* Bg = &g_B[l][li][0][0][0];
    const unsigned base = *((volatile unsigned*)&g_phase);

#pragma unroll 1
    for (int k = 0; k < NTICK; ++k) {
        const int t = k - l;
        const bool active = (t >= 0) && (t < Tv);
        const int rp = (k + 1) & 1;
        const int wp = k & 1;

        if (active) {
            const __nv_bfloat16* Ag = &g_A[l][rp][0][0][0];

            auto stage = [&](int s) {
                uint32_t buf = sm0 + (uint32_t)(s % 3) * STAGE_BYTES;
                const char* gaB = (const char*)Ag + (size_t)s * (KCH * 2);
                const char* gbB = (const char*)Bg + (size_t)s * (KCH * 2);
#pragma unroll
                for (int i2 = 0; i2 < 6; ++i2) {
                    int i = tid + i2 * BLK;          // 0..3071
                    int c16 = i & 7;
                    int rl = i >> 3;                 // 0..383
                    uint32_t dst; const char* src;
                    if (rl < 128) {                  // A planes (hi, lo), 64 rows each
                        int hl = rl >> 6, r = rl & 63;
                        dst = buf + (uint32_t)(hl * OFF_ALO + r * AROWB + c16 * 16);
                        src = gaB + ((size_t)hl * 128 + 64 * mhalf + r) * (KREAL * 2)
                                  + c16 * 16;
                    } else {                         // W planes (hi, lo), 128 rows each
                        int rb = rl - 128;
                        int hl = rb >> 7, r = rb & 127;
                        dst = buf + (uint32_t)(OFF_WHI + hl * 18432 + r * AROWB + c16 * 16);
                        src = gbB + ((size_t)hl * 128 + r) * (KREAL * 2) + c16 * 16;
                    }
                    cp16(dst, src);
                }
                asm volatile("cp.async.commit_group;");
            };

            float acc[4][4];
#pragma unroll
            for (int g = 0; g < 4; ++g)
#pragma unroll
                for (int e = 0; e < 4; ++e) acc[g][e] = 0.f;

            stage(0); stage(1);
#pragma unroll 1
            for (int c = 0; c < NCHUNK; ++c) {
                if (c < NCHUNK - 1) asm volatile("cp.async.wait_group 1;");
                else                asm volatile("cp.async.wait_group 0;");
                __syncthreads();
                if (c + 2 < NCHUNK) stage(c + 2);

                const uint32_t st = sm0 + (uint32_t)(c % 3) * STAGE_BYTES;
#pragma unroll
                for (int ks = 0; ks < KCH / 16; ++ks) {
                    const uint32_t kb = (uint32_t)(ks * 32);
                    uint32_t ahi[4], alo[4];
                    LDMX4(ahi, st + OFF_AHI + aoff + kb);
                    LDMX4(alo, st + OFF_ALO + aoff + kb);
                    uint32_t wh0[4], wh1[4], wl0[4], wl1[4];
                    LDMX4(wh0, st + OFF_WHI + boff0 + kb);
                    LDMX4(wh1, st + OFF_WHI + boff1 + kb);
                    LDMX4(wl0, st + OFF_WLO + boff0 + kb);
                    LDMX4(wl1, st + OFF_WLO + boff1 + kb);
                    MMA16816(acc[0], ahi, wh0[0], wh0[1]);
                    MMA16816(acc[1], ahi, wh0[2], wh0[3]);
                    MMA16816(acc[2], ahi, wh1[0], wh1[1]);
                    MMA16816(acc[3], ahi, wh1[2], wh1[3]);
                    MMA16816(acc[0], alo, wh0[0], wh0[1]);
                    MMA16816(acc[1], alo, wh0[2], wh0[3]);
                    MMA16816(acc[2], alo, wh1[0], wh1[1]);
                    MMA16816(acc[3], alo, wh1[2], wh1[3]);
                    MMA16816(acc[0], ahi, wl0[0], wl0[1]);
                    MMA16816(acc[1], ahi, wl0[2], wl0[3]);
                    MMA16816(acc[2], ahi, wl1[0], wl1[1]);
                    MMA16816(acc[3], ahi, wl1[2], wl1[3]);
                }
            }

            // ---------- epilogue ----------
            const float* hrd = g_hst[l][rp];
            float*       hwr = g_hst[l][wp];
            const int u0 = 8 * nw + (lane & 3) * 2;

#pragma unroll
            for (int rr = 0; rr < 2; ++rr) {
                const int m = 64 * mhalf + 16 * mw + (lane >> 2) + 8 * rr;
                float hv[2];
#pragma unroll
                for (int up = 0; up < 2; ++up) {
                    const int u = u0 + up, e = 2 * rr + up;
                    float r = sigf(acc[0][e] + sb[u]);
                    float z = sigf(acc[1][e] + sb[32 + u]);
                    float n = tanh_fast(acc[2][e] + sb[64 + u]
                                        + r * (acc[3][e] + sb[96 + u]));
                    float hp = hrd[(size_t)m * Hv + J0 + u];
                    hv[up] = (1.f - z) * n + z * hp;
                }
                const int j0 = J0 + u0;
                if (l == 2) {
                    float2 xv = *(const float2*)(x + ((size_t)m * Tv + t) * Hv + j0);
                    if (xv.x == 0.f) hv[0] = 0.f;
                    if (xv.y == 0.f) hv[1] = 0.f;
                    *(float2*)(y + ((size_t)m * Tv + t) * Hv + j0) =
                        make_float2(hv[0], hv[1]);
                }
                *(float2*)(hwr + (size_t)m * Hv + j0) = make_float2(hv[0], hv[1]);

                __nv_bfloat16 h0 = __float2bfloat16(hv[0]);
                __nv_bfloat16 h1 = __float2bfloat16(hv[1]);
                __nv_bfloat16 L0 = __float2bfloat16(hv[0] - __bfloat162float(h0));
                __nv_bfloat16 L1 = __float2bfloat16(hv[1] - __bfloat162float(h1));
                unsigned hp32 = (unsigned)__bfloat16_as_ushort(h0)
                              | ((unsigned)__bfloat16_as_ushort(h1) << 16);
                unsigned lp32 = (unsigned)__bfloat16_as_ushort(L0)
                              | ((unsigned)__bfloat16_as_ushort(L1) << 16);
                *(unsigned*)&g_A[l][wp][0][m][512 + j0] = hp32;   // self h-half
                *(unsigned*)&g_A[l][wp][1][m][512 + j0] = lp32;
                if (l < 2) {                                      // next-layer x-half
                    *(unsigned*)&g_A[l + 1][wp][0][m][j0] = hp32;
                    *(unsigned*)&g_A[l + 1][wp][1][m][j0] = lp32;
                }
            }
        }

        // layer-0 CTAs stage x_{k+1} into next parity's A0 x-region
        if (l == 0 && (k + 1) < Tv && tid < 256) {
            const int row = tid >> 2;
            const int kc0 = (tid & 3) * 8;
            const int m = 64 * mhalf + row;
            const float* xs = x + ((size_t)m * Tv + (k + 1)) * Hv + 32 * li + kc0;
            unsigned hp[4], lp[4];
#pragma unroll
            for (int q = 0; q < 4; ++q) {
                float v0 = xs[2 * q], v1 = xs[2 * q + 1];
                __nv_bfloat16 h0 = __float2bfloat16(v0);
                __nv_bfloat16 h1 = __float2bfloat16(v1);
                __nv_bfloat16 L0 = __float2bfloat16(v0 - __bfloat162float(h0));
                __nv_bfloat16 L1 = __float2bfloat16(v1 - __bfloat162float(h1));
                hp[q] = (unsigned)__bfloat16_as_ushort(h0)
                      | ((unsigned)__bfloat16_as_ushort(h1) << 16);
                lp[q] = (unsigned)__bfloat16_as_ushort(L0)
                      | ((unsigned)__bfloat16_as_ushort(L1) << 16);
            }
            *(uint4*)&g_A[0][wp][0][m][32 * li + kc0] =
                make_uint4(hp[0], hp[1], hp[2], hp[3]);
            *(uint4*)&g_A[0][wp][1][m][32 * li + kc0] =
                make_uint4(lp[0], lp[1], lp[2], lp[3]);
        }

        gsync(base + 1 + k);
    }
}

extern "C" void kernel_launch(void* const* d_in, const int* in_sizes, int n_in,
                              void* d_out, int out_size) {
    (void)in_sizes; (void)n_in; (void)out_size;
    const float* x = (const float*)d_in[0];
    gru_prep<<<256, 256>>>(x,
        (const float*)d_in[1], (const float*)d_in[2],
        (const float*)d_in[5], (const float*)d_in[6],
        (const float*)d_in[9], (const float*)d_in[10]);
    cudaFuncSetAttribute(gru_tc, cudaFuncAttributeMaxDynamicSharedMemorySize, SMEM_TOTAL);
    gru_tc<<<NCTA, BLK, SMEM_TOTAL>>>(x,
        (const float*)d_in[3],  (const float*)d_in[4],
        (const float*)d_in[7],  (const float*)d_in[8],
        (const float*)d_in[11], (const float*)d_in[12],
        (float*)d_out);
}

// round 10
// speedup vs baseline: 6.3331x; 1.0570x over previous
#include <cuda_runtime.h>
#include <cuda_bf16.h>
#include <cstdint>

// 3-layer GRU (r,z,n), B=128, T=512, H=512, fp32 — bf16 hi/lo mma.sync, v4.
// Wavefront: tick k -> layer l computes t = k - l; one grid barrier per tick.
// 96 CTAs = 3 layers x 16 col-tiles (32 units) x 2 batch halves; 16 warps.
// D[64,128] = sum over K=1024 of a_hi*w_hi + a_lo*w_hi + a_hi*w_lo.
// v4: 4-stage cp.async ring (distance-3 prefetch), cross-tick W prefetch
// (W is tick-invariant: next tick's first 3 W chunks fetched before the grid
// barrier), h-state in registers (thread-private), l2 mask prefetched.

#define Bv 128
#define Tv 512
#define Hv 512
#define NLAYER 3
#define CPL 16
#define NCTA 96
#define BLK 512
#define NTICK (Tv + 2)
#define KREAL 1024
#define KCH 64
#define NCHUNK (KREAL / KCH)   // 16
#define AROWB 144
#define OFF_ALO 9216           // 64*144
#define OFF_WHI 18432
#define STAGE_BYTES 55296
#define SMEM_TOTAL (512 + 4 * STAGE_BYTES)

__device__ __nv_bfloat16 g_B[NLAYER][CPL][2][128][KREAL];  // [hl][n][k]
__device__ __nv_bfloat16 g_A[NLAYER][2][2][Bv][KREAL];     // [parity][hl][m][k]
__device__ unsigned g_count = 0;
__device__ unsigned g_phase = 0;

__device__ __forceinline__ uint32_t smem_u32(const void* p) {
    uint32_t a;
    asm("{ .reg .u64 t; cvta.to.shared.u64 t, %1; cvt.u32.u64 %0, t; }" : "=r"(a) : "l"(p));
    return a;
}
__device__ __forceinline__ void cp16(uint32_t s, const void* g) {
    asm volatile("cp.async.cg.shared.global [%0], [%1], 16;" :: "r"(s), "l"(g));
}
__device__ __forceinline__ float sigf(float x) { return 1.f / (1.f + __expf(-x)); }
__device__ __forceinline__ float tanh_fast(float x) {
    x = fminf(fmaxf(x, -15.f), 15.f);
    float t = __expf(2.f * x);
    return (t - 1.f) / (t + 1.f);
}
__device__ __forceinline__ void gsync(unsigned target) {
    __syncthreads();
    if (threadIdx.x == 0) {
        __threadfence();
        unsigned a = atomicAdd(&g_count, 1u);
        if (a == NCTA - 1) {
            g_count = 0u;
            __threadfence();
            atomicAdd(&g_phase, 1u);
        } else {
            while (*((volatile unsigned*)&g_phase) < target) __nanosleep(32);
        }
    }
    __syncthreads();
}

#define MMA16816(d, a, b0, b1) \
    asm volatile("mma.sync.aligned.m16n8k16.row.col.f32.bf16.bf16.f32 " \
        "{%0,%1,%2,%3}, {%4,%5,%6,%7}, {%8,%9}, {%0,%1,%2,%3};" \
        : "+f"((d)[0]), "+f"((d)[1]), "+f"((d)[2]), "+f"((d)[3]) \
        : "r"((a)[0]), "r"((a)[1]), "r"((a)[2]), "r"((a)[3]), \
          "r"(b0), "r"(b1))

#define LDMX4(r, a) \
    asm volatile("ldmatrix.sync.aligned.m8n8.x4.shared.b16 {%0,%1,%2,%3}, [%4];" \
        : "=r"((r)[0]), "=r"((r)[1]), "=r"((r)[2]), "=r"((r)[3]) : "r"(a))

// ---------------- prep ----------------
__global__ void gru_prep(const float* __restrict__ x,
    const float* __restrict__ Wih0, const float* __restrict__ Whh0,
    const float* __restrict__ Wih1, const float* __restrict__ Whh1,
    const float* __restrict__ Wih2, const float* __restrict__ Whh2)
{
    const float* WI[3] = {Wih0, Wih1, Wih2};
    const float* WH[3] = {Whh0, Whh1, Whh2};
    const long gsz = (long)gridDim.x * blockDim.x;
    const long gid = (long)blockIdx.x * blockDim.x + threadIdx.x;

    const long BTOT = (long)NLAYER * CPL * 2 * 128 * KREAL;
    for (long idx = gid; idx < BTOT; idx += gsz) {
        int k   = (int)(idx & (KREAL - 1));
        long r0 = idx >> 10;
        int n   = (int)(r0 & 127);
        long r1 = r0 >> 7;
        int hl  = (int)(r1 & 1);
        long r2 = r1 >> 1;
        int li  = (int)(r2 % CPL);
        int l   = (int)(r2 / CPL);
        int gate = n >> 5, u = n & 31, j = li * 32 + u;
        int half = k >> 9, kk = k & 511;
        float wv = 0.f;
        if (half == 0) {
            if (gate < 3) wv = WI[l][(size_t)(gate * Hv + j) * Hv + kk];
        } else {
            if (gate == 0)      wv = WH[l][(size_t)(0 * Hv + j) * Hv + kk];
            else if (gate == 1) wv = WH[l][(size_t)(1 * Hv + j) * Hv + kk];
            else if (gate == 3) wv = WH[l][(size_t)(2 * Hv + j) * Hv + kk];
        }
        __nv_bfloat16 hi = __float2bfloat16(wv);
        (&g_B[0][0][0][0][0])[idx] = (hl == 0) ? hi
            : __float2bfloat16(wv - __bfloat162float(hi));
    }
    const long ATOT = (long)NLAYER * 2 * 2 * Bv * KREAL;
    for (long idx = gid; idx < ATOT; idx += gsz) {
        int k = (int)(idx & (KREAL - 1));
        long r0 = idx >> 10;
        int m = (int)(r0 & 127);
        long r1 = r0 >> 7;
        int hl = (int)(r1 & 1);
        int p  = (int)((r1 >> 1) & 1);
        int l  = (int)(r1 >> 2);
        __nv_bfloat16 out = __float2bfloat16(0.f);
        if (l == 0 && p == 1 && k < 512) {
            float v = x[((size_t)m * Tv) * Hv + k];
            __nv_bfloat16 hi = __float2bfloat16(v);
            out = (hl == 0) ? hi : __float2bfloat16(v - __bfloat162float(hi));
        }
        (&g_A[0][0][0][0][0])[idx] = out;
    }
}

// ---------------- main persistent HMMA kernel ----------------
__global__ void __launch_bounds__(BLK, 1) gru_tc(
    const float* __restrict__ x,
    const float* __restrict__ bih0, const float* __restrict__ bhh0,
    const float* __restrict__ bih1, const float* __restrict__ bhh1,
    const float* __restrict__ bih2, const float* __restrict__ bhh2,
    float* __restrict__ y)
{
    extern __shared__ char smem[];
    const uint32_t sm0 = smem_u32(smem) + 512;
    const int tid  = threadIdx.x;
    const int lane = tid & 31;
    const int wid  = tid >> 5;
    const int mw   = wid >> 2;          // 0..3
    const int nw   = wid & 3;           // 0..3
    const int l     = blockIdx.x >> 5;
    const int li    = (blockIdx.x >> 1) & 15;
    const int mhalf = blockIdx.x & 1;
    const int J0    = li * 32;

    const float* bihL = (l == 0) ? bih0 : (l == 1) ? bih1 : bih2;
    const float* bhhL = (l == 0) ? bhh0 : (l == 1) ? bhh1 : bhh2;

    float* sb = (float*)smem;
    if (tid < 32) {
        int j = J0 + tid;
        sb[tid]      = bihL[0 * Hv + j] + bhhL[0 * Hv + j];
        sb[32 + tid] = bihL[1 * Hv + j] + bhhL[1 * Hv + j];
        sb[64 + tid] = bihL[2 * Hv + j];
        sb[96 + tid] = bhhL[2 * Hv + j];
    }
    __syncthreads();

    const uint32_t aoff = (uint32_t)((16 * mw + (lane & 15)) * AROWB + (lane >> 4) * 16);
    const uint32_t boff0 = (uint32_t)((32 * (lane >> 4) + 8 * nw + (lane & 7)) * AROWB
                                      + ((lane >> 3) & 1) * 16);
    const uint32_t boff1 = boff0 + 64u * AROWB;

    const __nv_bfloat16* Bg = &g_B[l][li][0][0][0];
    const unsigned base = *((volatile unsigned*)&g_phase);

    // epilogue geometry + register-resident h state (thread-private slice)
    const int u0 = 8 * nw + (lane & 3) * 2;
    const int m0 = 64 * mhalf + 16 * mw + (lane >> 2);
    const int j0 = J0 + u0;
    float hloc[4] = {0.f, 0.f, 0.f, 0.f};   // [rr*2+up]

    // ---- staging helpers ----
    auto stageW = [&](int s) {
        uint32_t buf = sm0 + (uint32_t)(s & 3) * STAGE_BYTES;
        const char* gbB = (const char*)Bg + (size_t)s * (KCH * 2);
#pragma unroll
        for (int i2 = 0; i2 < 4; ++i2) {
            int i = tid + i2 * BLK;           // 0..2047
            int c16 = i & 7;
            int rb = i >> 3;                  // 0..255
            int hl = rb >> 7, r = rb & 127;
            cp16(buf + (uint32_t)(OFF_WHI + hl * 18432 + r * AROWB + c16 * 16),
                 gbB + ((size_t)hl * 128 + r) * (KREAL * 2) + c16 * 16);
        }
    };

#pragma unroll 1
    for (int k = 0; k < NTICK; ++k) {
        const int t = k - l;
        const bool active = (t >= 0) && (t < Tv);
        const int rp = (k + 1) & 1;
        const int wp = k & 1;

        if (active) {
            const __nv_bfloat16* Ag = &g_A[l][rp][0][0][0];

            auto stageA = [&](int s) {
                uint32_t buf = sm0 + (uint32_t)(s & 3) * STAGE_BYTES;
                const char* gaB = (const char*)Ag + (size_t)s * (KCH * 2);
#pragma unroll
                for (int i2 = 0; i2 < 2; ++i2) {
                    int i = tid + i2 * BLK;       // 0..1023
                    int c16 = i & 7;
                    int rb = i >> 3;              // 0..127
                    int hl = rb >> 6, r = rb & 63;
                    cp16(buf + (uint32_t)(hl * OFF_ALO + r * AROWB + c16 * 16),
                         gaB + ((size_t)hl * 128 + 64 * mhalf + r) * (KREAL * 2) + c16 * 16);
                }
            };

            // cold start only (l==0, k==0): W not prefetched by a prior tick
            if (l == 0 && k == 0) { stageW(0); stageW(1); stageW(2); }
            stageA(0); asm volatile("cp.async.commit_group;");
            stageA(1); asm volatile("cp.async.commit_group;");
            stageA(2); asm volatile("cp.async.commit_group;");

            // prefetch l==2 mask values for the epilogue
            float2 xm[2];
            if (l == 2) {
                xm[0] = *(const float2*)(x + ((size_t)m0 * Tv + t) * Hv + j0);
                xm[1] = *(const float2*)(x + ((size_t)(m0 + 8) * Tv + t) * Hv + j0);
            }

            float acc[4][4];
#pragma unroll
            for (int g = 0; g < 4; ++g)
#pragma unroll
                for (int e = 0; e < 4; ++e) acc[g][e] = 0.f;

#pragma unroll 1
            for (int c = 0; c < NCHUNK; ++c) {
                const int rem = NCHUNK - 1 - c;
                if (rem >= 2)      asm volatile("cp.async.wait_group 2;");
                else if (rem == 1) asm volatile("cp.async.wait_group 1;");
                else               asm volatile("cp.async.wait_group 0;");
                __syncthreads();
                if (c + 3 < NCHUNK) {
                    stageW(c + 3); stageA(c + 3);
                    asm volatile("cp.async.commit_group;");
                }

                const uint32_t st = sm0 + (uint32_t)(c & 3) * STAGE_BYTES;
#pragma unroll
                for (int ks = 0; ks < KCH / 16; ++ks) {
                    const uint32_t kb = (uint32_t)(ks * 32);
                    uint32_t ahi[4], alo[4];
                    LDMX4(ahi, st + aoff + kb);
                    LDMX4(alo, st + OFF_ALO + aoff + kb);
                    uint32_t wh0[4], wh1[4], wl0[4], wl1[4];
                    LDMX4(wh0, st + OFF_WHI + boff0 + kb);
                    LDMX4(wh1, st + OFF_WHI + boff1 + kb);
                    LDMX4(wl0, st + OFF_WHI + 18432 + boff0 + kb);
                    LDMX4(wl1, st + OFF_WHI + 18432 + boff1 + kb);
                    MMA16816(acc[0], ahi, wh0[0], wh0[1]);
                    MMA16816(acc[1], ahi, wh0[2], wh0[3]);
                    MMA16816(acc[2], ahi, wh1[0], wh1[1]);
                    MMA16816(acc[3], ahi, wh1[2], wh1[3]);
                    MMA16816(acc[0], alo, wh0[0], wh0[1]);
                    MMA16816(acc[1], alo, wh0[2], wh0[3]);
                    MMA16816(acc[2], alo, wh1[0], wh1[1]);
                    MMA16816(acc[3], alo, wh1[2], wh1[3]);
                    MMA16816(acc[0], ahi, wl0[0], wl0[1]);
                    MMA16816(acc[1], ahi, wl0[2], wl0[3]);
                    MMA16816(acc[2], ahi, wl1[0], wl1[1]);
                    MMA16816(acc[3], ahi, wl1[2], wl1[3]);
                }
            }

            // prefetch next tick's W into the now-free buffers 0..2,
            // overlapping the epilogue and the grid barrier
            if ((k + 1 - l) >= 0 && (k + 1 - l) < Tv) {
                stageW(0); stageW(1); stageW(2);
            }

            // ---------- epilogue ----------
#pragma unroll
            for (int rr = 0; rr < 2; ++rr) {
                const int m = m0 + 8 * rr;
                float hv[2];
#pragma unroll
                for (int up = 0; up < 2; ++up) {
                    const int u = u0 + up, e = 2 * rr + up;
                    float r = sigf(acc[0][e] + sb[u]);
                    float z = sigf(acc[1][e] + sb[32 + u]);
                    float n = tanh_fast(acc[2][e] + sb[64 + u]
                                        + r * (acc[3][e] + sb[96 + u]));
                    hv[up] = (1.f - z) * n + z * hloc[rr * 2 + up];
                }
                if (l == 2) {
                    if (xm[rr].x == 0.f) hv[0] = 0.f;
                    if (xm[rr].y == 0.f) hv[1] = 0.f;
                    *(float2*)(y + ((size_t)m * Tv + t) * Hv + j0) =
                        make_float2(hv[0], hv[1]);
                }
                hloc[rr * 2 + 0] = hv[0];
                hloc[rr * 2 + 1] = hv[1];

                __nv_bfloat16 h0 = __float2bfloat16(hv[0]);
                __nv_bfloat16 h1 = __float2bfloat16(hv[1]);
                __nv_bfloat16 L0 = __float2bfloat16(hv[0] - __bfloat162float(h0));
                __nv_bfloat16 L1 = __float2bfloat16(hv[1] - __bfloat162float(h1));
                unsigned hp32 = (unsigned)__bfloat16_as_ushort(h0)
                              | ((unsigned)__bfloat16_as_ushort(h1) << 16);
                unsigned lp32 = (unsigned)__bfloat16_as_ushort(L0)
                              | ((unsigned)__bfloat16_as_ushort(L1) << 16);
                *(unsigned*)&g_A[l][wp][0][m][512 + j0] = hp32;   // self h-half
                *(unsigned*)&g_A[l][wp][1][m][512 + j0] = lp32;
                if (l < 2) {                                      // next-layer x-half
                    *(unsigned*)&g_A[l + 1][wp][0][m][j0] = hp32;
                    *(unsigned*)&g_A[l + 1][wp][1][m][j0] = lp32;
                }
            }
        } else {
            // inactive tick: still prefetch W if next tick becomes active
            if ((k + 1 - l) >= 0 && (k + 1 - l) < Tv) {
                stageW(0); stageW(1); stageW(2);
            }
        }

        // layer-0 CTAs stage x_{k+1} into next parity's A0 x-region
        if (l == 0 && (k + 1) < Tv && tid < 256) {
            const int row = tid >> 2;
            const int kc0 = (tid & 3) * 8;
            const int m = 64 * mhalf + row;
            const float* xs = x + ((size_t)m * Tv + (k + 1)) * Hv + 32 * li + kc0;
            unsigned hp[4], lp[4];
#pragma unroll
            for (int q = 0; q < 4; ++q) {
                float v0 = xs[2 * q], v1 = xs[2 * q + 1];
                __nv_bfloat16 h0 = __float2bfloat16(v0);
                __nv_bfloat16 h1 = __float2bfloat16(v1);
                __nv_bfloat16 L0 = __float2bfloat16(v0 - __bfloat162float(h0));
                __nv_bfloat16 L1 = __float2bfloat16(v1 - __bfloat162float(h1));
                hp[q] = (unsigned)__bfloat16_as_ushort(h0)
                      | ((unsigned)__bfloat16_as_ushort(h1) << 16);
                lp[q] = (unsigned)__bfloat16_as_ushort(L0)
                      | ((unsigned)__bfloat16_as_ushort(L1) << 16);
            }
            *(uint4*)&g_A[0][wp][0][m][32 * li + kc0] =
                make_uint4(hp[0], hp[1], hp[2], hp[3]);
            *(uint4*)&g_A[0][wp][1][m][32 * li + kc0] =
                make_uint4(lp[0], lp[1], lp[2], lp[3]);
        }

        gsync(base + 1 + k);
    }
}

extern "C" void kernel_launch(void* const* d_in, const int* in_sizes, int n_in,
                              void* d_out, int out_size) {
    (void)in_sizes; (void)n_in; (void)out_size;
    const float* x = (const float*)d_in[0];
    gru_prep<<<256, 256>>>(x,
        (const float*)d_in[1], (const float*)d_in[2],
        (const float*)d_in[5], (const float*)d_in[6],
        (const float*)d_in[9], (const float*)d_in[10]);
    cudaFuncSetAttribute(gru_tc, cudaFuncAttributeMaxDynamicSharedMemorySize, SMEM_TOTAL);
    gru_tc<<<NCTA, BLK, SMEM_TOTAL>>>(x,
        (const float*)d_in[3],  (const float*)d_in[4],
        (const float*)d_in[7],  (const float*)d_in[8],
        (const float*)d_in[11], (const float*)d_in[12],
        (float*)d_out);
}